// round 15
// baseline (speedup 1.0000x reference)
#include <cuda_runtime.h>
#include <cuda_fp16.h>
#include <stdint.h>

#define NIN  128
#define NOUT 128
#define MAX_N 100000
#define MAX_E 1600000
#define SCAN_B 1024
#define MAX_SCAN_BLOCKS 128

// ------------- scratch: __device__ globals ------------------------------------
__device__ __align__(16) int     g_cnt[MAX_N];
__device__ __align__(16) int     g_indptr[MAX_N];
__device__ __align__(16) int     g_blksum[MAX_SCAN_BLOCKS];
__device__ __align__(16) int     g_flag[MAX_SCAN_BLOCKS];
__device__ __align__(16) float   g_dinv[MAX_N];
__device__ __align__(16) int     g_rank[MAX_E];   // edge rank within its dst
__device__ __align__(16) int     g_eidx[MAX_E];
__device__ __align__(16) __half2 g_h[(size_t)MAX_N * (NOUT / 2)];  // fp16 g = dinv[m]*(x@W^T)

// ---------------- CSR build (edge_index is int32) -----------------------------

// Returning atomic: rank = old count. Block 0 zeroes scan flags.
__global__ void cnt_count_kernel(const int* __restrict__ ei, int E, int n) {
    if (blockIdx.x == 0 && threadIdx.x < MAX_SCAN_BLOCKS) g_flag[threadIdx.x] = 0;
    int e = blockIdx.x * blockDim.x + threadIdx.x;
    if (e < E) {
        int dst = ei[E + e];
        if ((unsigned)dst < (unsigned)n)
            g_rank[e] = atomicAdd(&g_cnt[dst], 1);
    }
}

// Fused scan + addback (decoupled lookback over <=98 resident blocks).
__global__ __launch_bounds__(SCAN_B) void scan_fused_kernel(int n) {
    __shared__ int warpsum[32];
    __shared__ int Pshared;
    int tid = threadIdx.x;
    int blk = blockIdx.x;
    int i = blk * SCAN_B + tid;
    int v = (i < n) ? g_cnt[i] : 0;
    int x = v;
    #pragma unroll
    for (int o = 1; o < 32; o <<= 1) {
        int t = __shfl_up_sync(0xFFFFFFFFu, x, o);
        if ((tid & 31) >= o) x += t;
    }
    if ((tid & 31) == 31) warpsum[tid >> 5] = x;
    __syncthreads();
    if (tid < 32) {
        int s = warpsum[tid];
        #pragma unroll
        for (int o = 1; o < 32; o <<= 1) {
            int t = __shfl_up_sync(0xFFFFFFFFu, s, o);
            if (tid >= o) s += t;
        }
        warpsum[tid] = s;
    }
    __syncthreads();
    int wid = tid >> 5;
    int base = (wid > 0) ? warpsum[wid - 1] : 0;
    int incl = base + x;

    if (tid == SCAN_B - 1) {
        g_blksum[blk] = incl;
        __threadfence();
        atomicExch(&g_flag[blk], 1);
    }
    if (tid < 32) {
        int s = 0;
        for (int j = tid; j < blk; j += 32) {
            while (atomicAdd(&g_flag[j], 0) == 0) { }
            s += g_blksum[j];
        }
        #pragma unroll
        for (int o = 16; o; o >>= 1) s += __shfl_down_sync(0xFFFFFFFFu, s, o);
        if (tid == 0) Pshared = s;
    }
    __syncthreads();
    if (i < n) {
        int p = Pshared + incl - v;
        g_indptr[i] = p;
        g_dinv[i] = rsqrtf((float)(v + 1));
    }
}

// Atomic-free fill: pos = indptr[dst] + rank[e].
__global__ void fill_kernel(const int* __restrict__ ei, int E, int n) {
    int e = blockIdx.x * blockDim.x + threadIdx.x;
    if (e < E) {
        int src = ei[e];
        int dst = ei[E + e];
        if ((unsigned)dst < (unsigned)n && (unsigned)src < (unsigned)n) {
            int pos = g_indptr[dst] + g_rank[e];
            if ((unsigned)pos < (unsigned)MAX_E) g_eidx[pos] = src;
        }
    }
}

// ---------------- fp16 mma GEMM: g_h = half( dinv[m] * (x @ W^T) ) ------------

__device__ __forceinline__ void mma16(float* c, uint32_t a0, uint32_t a1, uint32_t a2,
                                      uint32_t a3, uint32_t b0, uint32_t b1) {
    asm volatile(
        "mma.sync.aligned.m16n8k16.row.col.f32.f16.f16.f32 "
        "{%0,%1,%2,%3}, {%4,%5,%6,%7}, {%8,%9}, {%0,%1,%2,%3};"
        : "+f"(c[0]), "+f"(c[1]), "+f"(c[2]), "+f"(c[3])
        : "r"(a0), "r"(a1), "r"(a2), "r"(a3), "r"(b0), "r"(b1));
}

#define KC 32
#define PHU 20   // row stride in u32 units (= 40 halfs: 32 data + 8 pad)

__global__ __launch_bounds__(256, 2) void gemm_mma_kernel(
    const float* __restrict__ x, const float* __restrict__ W, int n)
{
    __shared__ uint32_t As[128 * PHU];
    __shared__ uint32_t Bs[128 * PHU];

    const int tid  = threadIdx.x;
    const int wid  = tid >> 5;
    const int lane = tid & 31;
    const int gq   = lane >> 2;
    const int tq   = lane & 3;
    const int warpM = wid & 3;
    const int warpN = wid >> 2;
    const int rowBase = blockIdx.x * 128;

    float acc[2][8][4];
    #pragma unroll
    for (int mt = 0; mt < 2; mt++)
        #pragma unroll
        for (int nt = 0; nt < 8; nt++)
            #pragma unroll
            for (int q = 0; q < 4; q++) acc[mt][nt][q] = 0.0f;

    #pragma unroll
    for (int chunk = 0; chunk < 4; chunk++) {
        #pragma unroll
        for (int it = 0; it < 4; it++) {
            int gid = tid + it * 256;
            int row = gid >> 3;
            int f4  = gid & 7;
            int gm = rowBase + row;
            float4 av = make_float4(0.f, 0.f, 0.f, 0.f);
            if (gm < n) av = *reinterpret_cast<const float4*>(&x[(size_t)gm * NIN + chunk * KC + f4 * 4]);
            __half2 a01 = __floats2half2_rn(av.x, av.y);
            __half2 a23 = __floats2half2_rn(av.z, av.w);
            As[row * PHU + f4 * 2]     = *reinterpret_cast<uint32_t*>(&a01);
            As[row * PHU + f4 * 2 + 1] = *reinterpret_cast<uint32_t*>(&a23);

            float4 bv = *reinterpret_cast<const float4*>(&W[(size_t)row * NIN + chunk * KC + f4 * 4]);
            __half2 b01 = __floats2half2_rn(bv.x, bv.y);
            __half2 b23 = __floats2half2_rn(bv.z, bv.w);
            Bs[row * PHU + f4 * 2]     = *reinterpret_cast<uint32_t*>(&b01);
            Bs[row * PHU + f4 * 2 + 1] = *reinterpret_cast<uint32_t*>(&b23);
        }
        __syncthreads();

        #pragma unroll
        for (int ks = 0; ks < 2; ks++) {
            int ko = ks * 8;
            uint32_t a[2][4];
            #pragma unroll
            for (int mt = 0; mt < 2; mt++) {
                int r0 = (warpM * 32 + mt * 16 + gq) * PHU;
                a[mt][0] = As[r0 + ko + tq];
                a[mt][1] = As[r0 + 8 * PHU + ko + tq];
                a[mt][2] = As[r0 + ko + tq + 4];
                a[mt][3] = As[r0 + 8 * PHU + ko + tq + 4];
            }
            #pragma unroll
            for (int nt = 0; nt < 8; nt++) {
                int nr = (warpN * 64 + nt * 8 + gq) * PHU;
                uint32_t b0 = Bs[nr + ko + tq];
                uint32_t b1 = Bs[nr + ko + tq + 4];
                #pragma unroll
                for (int mt = 0; mt < 2; mt++)
                    mma16(acc[mt][nt], a[mt][0], a[mt][1], a[mt][2], a[mt][3], b0, b1);
            }
        }
        __syncthreads();
    }

    #pragma unroll
    for (int mt = 0; mt < 2; mt++) {
        int r0 = rowBase + warpM * 32 + mt * 16 + gq;
        int r1 = r0 + 8;
        float s0 = (r0 < n) ? g_dinv[r0] : 0.0f;
        float s1 = (r1 < n) ? g_dinv[r1] : 0.0f;
        #pragma unroll
        for (int nt = 0; nt < 8; nt++) {
            int c = warpN * 64 + nt * 8 + 2 * tq;
            if (r0 < n)
                g_h[(size_t)r0 * 64 + (c >> 1)] =
                    __floats2half2_rn(acc[mt][nt][0] * s0, acc[mt][nt][1] * s0);
            if (r1 < n)
                g_h[(size_t)r1 * 64 + (c >> 1)] =
                    __floats2half2_rn(acc[mt][nt][2] * s1, acc[mt][nt][3] * s1);
        }
    }
}

// ---------------- Pull aggregation: TWO warps per destination row -------------
// Each warp covers 128B (half the row) with 4B=half2 per lane. Doubles warp
// parallelism for this latency-bound gather; per-warp chain length unchanged.
// out[i] = dinv[i] * ( g[i] + sum_e g[src_e] ) + b      (g pre-scaled by dinv)
__global__ __launch_bounds__(256) void aggregate_kernel(
    float* __restrict__ out, const float* __restrict__ b, int n)
{
    const uint32_t* gh = reinterpret_cast<const uint32_t*>(g_h);  // half2 units
    int gw   = (blockIdx.x * blockDim.x + threadIdx.x) >> 5;
    int lane = threadIdx.x & 31;
    int node = gw >> 1;
    int halfId = gw & 1;
    if (node >= n) return;

    int col = halfId * 32 + lane;          // half2 column 0..63
    size_t rowSelf = (size_t)node * 64 + col;

    float2 acc;
    {
        __half2 h = *reinterpret_cast<const __half2*>(&gh[rowSelf]);
        acc = __half22float2(h);
    }
    int beg = g_indptr[node];
    int num = g_cnt[node];

    int e = 0;
    for (; e + 7 < num; e += 8) {
        int      s[8];
        uint32_t v[8];
        #pragma unroll
        for (int q = 0; q < 8; q++) s[q] = g_eidx[beg + e + q];
        #pragma unroll
        for (int q = 0; q < 8; q++) v[q] = gh[(size_t)s[q] * 64 + col];
        #pragma unroll
        for (int q = 0; q < 8; q++) {
            float2 f = __half22float2(*reinterpret_cast<__half2*>(&v[q]));
            acc.x += f.x; acc.y += f.y;
        }
    }
    for (; e < num; e++) {
        int s0 = g_eidx[beg + e];
        uint32_t v = gh[(size_t)s0 * 64 + col];
        float2 f = __half22float2(*reinterpret_cast<__half2*>(&v));
        acc.x += f.x; acc.y += f.y;
    }

    float sdi = g_dinv[node];
    float2 bb = reinterpret_cast<const float2*>(b)[col];
    float2 o;
    o.x = fmaf(acc.x, sdi, bb.x);
    o.y = fmaf(acc.y, sdi, bb.y);
    reinterpret_cast<float2*>(out)[(size_t)node * 64 + col] = o;
}

// ---------------- launch: scan -> {gemm || fill} -> aggregate -----------------
// Submission order: cnt(0), scan(1), fill(2), gemm(3=profiled), agg(4).

extern "C" void kernel_launch(void* const* d_in, const int* in_sizes, int n_in,
                              void* d_out, int out_size) {
    const float* x  = (const float*)d_in[0];
    const int*   ei = (const int*)d_in[1];     // int32 (JAX x64 disabled)
    const float* W  = (const float*)d_in[3];
    const float* b  = (const float*)d_in[4];
    float*       out = (float*)d_out;

    int n = in_sizes[0] / NIN;
    int E = in_sizes[1] / 2;
    int nb = (n + SCAN_B - 1) / SCAN_B;

    cudaStream_t s2;
    cudaEvent_t evS, evJ;
    cudaStreamCreateWithFlags(&s2, cudaStreamNonBlocking);
    cudaEventCreateWithFlags(&evS, cudaEventDisableTiming);
    cudaEventCreateWithFlags(&evJ, cudaEventDisableTiming);

    // Chain prefix: memset -> cnt(+rank) -> scan (produces indptr, dinv).
    void* cnt_ptr = nullptr;
    cudaGetSymbolAddress(&cnt_ptr, g_cnt);
    cudaMemsetAsync(cnt_ptr, 0, (size_t)n * sizeof(int));
    cnt_count_kernel<<<(E + 255) / 256, 256>>>(ei, E, n);        // idx 0
    scan_fused_kernel<<<nb, SCAN_B>>>(n);                        // idx 1
    cudaEventRecord(evS, 0);

    fill_kernel<<<(E + 255) / 256, 256>>>(ei, E, n);             // idx 2

    // gemm on side stream (waits scan only) - submitted at idx 3 for profiling.
    cudaStreamWaitEvent(s2, evS, 0);
    gemm_mma_kernel<<<(n + 127) / 128, 256, 0, s2>>>(x, W, n);   // idx 3
    cudaEventRecord(evJ, s2);

    // Join, then aggregate (2 warps per node).
    cudaStreamWaitEvent(0, evJ, 0);
    long long agg_threads = (long long)n * 64;
    aggregate_kernel<<<(int)((agg_threads + 255) / 256), 256>>>(out, b, n);  // idx 4
}

// round 17
// speedup vs baseline: 1.2074x; 1.2074x over previous
#include <cuda_runtime.h>
#include <cuda_fp16.h>
#include <stdint.h>

#define NIN  128
#define NOUT 128
#define MAX_N 100000
#define MAX_E 1600000
#define SCAN_B 1024
#define MAX_SCAN_BLOCKS 128

// ------------- scratch: __device__ globals ------------------------------------
__device__ __align__(16) int     g_cnt[MAX_N];
__device__ __align__(16) int     g_indptr[MAX_N];
__device__ __align__(16) int     g_blksum[MAX_SCAN_BLOCKS];
__device__ __align__(16) int     g_flag[MAX_SCAN_BLOCKS];
__device__ __align__(16) float   g_dinv[MAX_N];
__device__ __align__(16) int     g_rank[MAX_E];
__device__ __align__(16) int     g_eidx[MAX_E];
__device__ __align__(16) __half2 g_h[(size_t)MAX_N * (NOUT / 2)];  // fp16 g = dinv[m]*(x@W^T)

// ---------------- CSR build (edge_index is int32) -----------------------------

__global__ void cnt_count_kernel(const int* __restrict__ ei, int E, int n) {
    if (blockIdx.x == 0 && threadIdx.x < MAX_SCAN_BLOCKS) g_flag[threadIdx.x] = 0;
    int e = blockIdx.x * blockDim.x + threadIdx.x;
    if (e < E) {
        int dst = ei[E + e];
        if ((unsigned)dst < (unsigned)n)
            g_rank[e] = atomicAdd(&g_cnt[dst], 1);
    }
}

__global__ __launch_bounds__(SCAN_B) void scan_fused_kernel(int n) {
    __shared__ int warpsum[32];
    __shared__ int Pshared;
    int tid = threadIdx.x;
    int blk = blockIdx.x;
    int i = blk * SCAN_B + tid;
    int v = (i < n) ? g_cnt[i] : 0;
    int x = v;
    #pragma unroll
    for (int o = 1; o < 32; o <<= 1) {
        int t = __shfl_up_sync(0xFFFFFFFFu, x, o);
        if ((tid & 31) >= o) x += t;
    }
    if ((tid & 31) == 31) warpsum[tid >> 5] = x;
    __syncthreads();
    if (tid < 32) {
        int s = warpsum[tid];
        #pragma unroll
        for (int o = 1; o < 32; o <<= 1) {
            int t = __shfl_up_sync(0xFFFFFFFFu, s, o);
            if (tid >= o) s += t;
        }
        warpsum[tid] = s;
    }
    __syncthreads();
    int wid = tid >> 5;
    int base = (wid > 0) ? warpsum[wid - 1] : 0;
    int incl = base + x;

    if (tid == SCAN_B - 1) {
        g_blksum[blk] = incl;
        __threadfence();
        atomicExch(&g_flag[blk], 1);
    }
    if (tid < 32) {
        int s = 0;
        for (int j = tid; j < blk; j += 32) {
            while (atomicAdd(&g_flag[j], 0) == 0) { }
            s += g_blksum[j];
        }
        #pragma unroll
        for (int o = 16; o; o >>= 1) s += __shfl_down_sync(0xFFFFFFFFu, s, o);
        if (tid == 0) Pshared = s;
    }
    __syncthreads();
    if (i < n) {
        int p = Pshared + incl - v;
        g_indptr[i] = p;
        g_dinv[i] = rsqrtf((float)(v + 1));
    }
}

// Atomic-free fill: pos = indptr[dst] + rank[e].
__global__ void fill_kernel(const int* __restrict__ ei, int E, int n) {
    int e = blockIdx.x * blockDim.x + threadIdx.x;
    if (e < E) {
        int src = ei[e];
        int dst = ei[E + e];
        if ((unsigned)dst < (unsigned)n && (unsigned)src < (unsigned)n) {
            int pos = g_indptr[dst] + g_rank[e];
            if ((unsigned)pos < (unsigned)MAX_E) g_eidx[pos] = src;
        }
    }
}

// ---------------- fp16 mma GEMM (R13-proven): g_h = half( dinv*(x@W^T) ) ------
// Depends only on g_cnt (dinv recomputed in epilogue) -> forks right after cnt.

__device__ __forceinline__ void mma16(float* c, uint32_t a0, uint32_t a1, uint32_t a2,
                                      uint32_t a3, uint32_t b0, uint32_t b1) {
    asm volatile(
        "mma.sync.aligned.m16n8k16.row.col.f32.f16.f16.f32 "
        "{%0,%1,%2,%3}, {%4,%5,%6,%7}, {%8,%9}, {%0,%1,%2,%3};"
        : "+f"(c[0]), "+f"(c[1]), "+f"(c[2]), "+f"(c[3])
        : "r"(a0), "r"(a1), "r"(a2), "r"(a3), "r"(b0), "r"(b1));
}

#define KC 32
#define PHU 20   // row stride in u32 units (= 40 halfs: 32 data + 8 pad)

__global__ __launch_bounds__(256, 2) void gemm_mma_kernel(
    const float* __restrict__ x, const float* __restrict__ W, int n)
{
    __shared__ uint32_t As[128 * PHU];
    __shared__ uint32_t Bs[128 * PHU];

    const int tid  = threadIdx.x;
    const int wid  = tid >> 5;
    const int lane = tid & 31;
    const int gq   = lane >> 2;
    const int tq   = lane & 3;
    const int warpM = wid & 3;
    const int warpN = wid >> 2;
    const int rowBase = blockIdx.x * 128;

    float acc[2][8][4];
    #pragma unroll
    for (int mt = 0; mt < 2; mt++)
        #pragma unroll
        for (int nt = 0; nt < 8; nt++)
            #pragma unroll
            for (int q = 0; q < 4; q++) acc[mt][nt][q] = 0.0f;

    #pragma unroll
    for (int chunk = 0; chunk < 4; chunk++) {
        #pragma unroll
        for (int it = 0; it < 4; it++) {
            int gid = tid + it * 256;
            int row = gid >> 3;
            int f4  = gid & 7;
            int gm = rowBase + row;
            float4 av = make_float4(0.f, 0.f, 0.f, 0.f);
            if (gm < n) av = *reinterpret_cast<const float4*>(&x[(size_t)gm * NIN + chunk * KC + f4 * 4]);
            __half2 a01 = __floats2half2_rn(av.x, av.y);
            __half2 a23 = __floats2half2_rn(av.z, av.w);
            As[row * PHU + f4 * 2]     = *reinterpret_cast<uint32_t*>(&a01);
            As[row * PHU + f4 * 2 + 1] = *reinterpret_cast<uint32_t*>(&a23);

            float4 bv = *reinterpret_cast<const float4*>(&W[(size_t)row * NIN + chunk * KC + f4 * 4]);
            __half2 b01 = __floats2half2_rn(bv.x, bv.y);
            __half2 b23 = __floats2half2_rn(bv.z, bv.w);
            Bs[row * PHU + f4 * 2]     = *reinterpret_cast<uint32_t*>(&b01);
            Bs[row * PHU + f4 * 2 + 1] = *reinterpret_cast<uint32_t*>(&b23);
        }
        __syncthreads();

        #pragma unroll
        for (int ks = 0; ks < 2; ks++) {
            int ko = ks * 8;
            uint32_t a[2][4];
            #pragma unroll
            for (int mt = 0; mt < 2; mt++) {
                int r0 = (warpM * 32 + mt * 16 + gq) * PHU;
                a[mt][0] = As[r0 + ko + tq];
                a[mt][1] = As[r0 + 8 * PHU + ko + tq];
                a[mt][2] = As[r0 + ko + tq + 4];
                a[mt][3] = As[r0 + 8 * PHU + ko + tq + 4];
            }
            #pragma unroll
            for (int nt = 0; nt < 8; nt++) {
                int nr = (warpN * 64 + nt * 8 + gq) * PHU;
                uint32_t b0 = Bs[nr + ko + tq];
                uint32_t b1 = Bs[nr + ko + tq + 4];
                #pragma unroll
                for (int mt = 0; mt < 2; mt++)
                    mma16(acc[mt][nt], a[mt][0], a[mt][1], a[mt][2], a[mt][3], b0, b1);
            }
        }
        __syncthreads();
    }

    // ---- epilogue: dinv from g_cnt (no scan dependency), scale, write g_h ----
    #pragma unroll
    for (int mt = 0; mt < 2; mt++) {
        int r0 = rowBase + warpM * 32 + mt * 16 + gq;
        int r1 = r0 + 8;
        float s0 = (r0 < n) ? rsqrtf((float)(g_cnt[r0] + 1)) : 0.0f;
        float s1 = (r1 < n) ? rsqrtf((float)(g_cnt[r1] + 1)) : 0.0f;
        #pragma unroll
        for (int nt = 0; nt < 8; nt++) {
            int c = warpN * 64 + nt * 8 + 2 * tq;
            if (r0 < n)
                g_h[(size_t)r0 * 64 + (c >> 1)] =
                    __floats2half2_rn(acc[mt][nt][0] * s0, acc[mt][nt][1] * s0);
            if (r1 < n)
                g_h[(size_t)r1 * 64 + (c >> 1)] =
                    __floats2half2_rn(acc[mt][nt][2] * s1, acc[mt][nt][3] * s1);
        }
    }
}

// ---------------- Pull aggregation: warp per node, pipelined eidx -------------
// out[i] = dinv[i] * ( g[i] + sum_e g[src_e] ) + b      (g pre-scaled by dinv)
__global__ __launch_bounds__(256) void aggregate_kernel(
    float* __restrict__ out, const float* __restrict__ b, int n)
{
    const uint2* gh2 = reinterpret_cast<const uint2*>(g_h);
    int w    = (blockIdx.x * blockDim.x + threadIdx.x) >> 5;
    int lane = threadIdx.x & 31;
    if (w >= n) return;

    float4 acc;
    {
        uint2 v = gh2[(size_t)w * 32 + lane];
        float2 f0 = __half22float2(*reinterpret_cast<__half2*>(&v.x));
        float2 f1 = __half22float2(*reinterpret_cast<__half2*>(&v.y));
        acc = make_float4(f0.x, f0.y, f1.x, f1.y);
    }
    int beg = g_indptr[w];
    int num = g_cnt[w];

    int e = 0;
    if (num >= 16) {
        int s[8];
        #pragma unroll
        for (int q = 0; q < 8; q++) s[q] = g_eidx[beg + q];
        for (; e + 15 < num; e += 8) {
            // prefetch next batch's indices while gathering current
            int sn[8];
            #pragma unroll
            for (int q = 0; q < 8; q++) sn[q] = g_eidx[beg + e + 8 + q];
            uint2 v[8];
            #pragma unroll
            for (int q = 0; q < 8; q++) v[q] = gh2[(size_t)s[q] * 32 + lane];
            #pragma unroll
            for (int q = 0; q < 8; q++) {
                float2 f0 = __half22float2(*reinterpret_cast<__half2*>(&v[q].x));
                float2 f1 = __half22float2(*reinterpret_cast<__half2*>(&v[q].y));
                acc.x += f0.x; acc.y += f0.y; acc.z += f1.x; acc.w += f1.y;
            }
            #pragma unroll
            for (int q = 0; q < 8; q++) s[q] = sn[q];
        }
        // drain the prefetched batch
        uint2 v[8];
        #pragma unroll
        for (int q = 0; q < 8; q++) v[q] = gh2[(size_t)s[q] * 32 + lane];
        #pragma unroll
        for (int q = 0; q < 8; q++) {
            float2 f0 = __half22float2(*reinterpret_cast<__half2*>(&v[q].x));
            float2 f1 = __half22float2(*reinterpret_cast<__half2*>(&v[q].y));
            acc.x += f0.x; acc.y += f0.y; acc.z += f1.x; acc.w += f1.y;
        }
        e += 8;
    }
    for (; e < num; e++) {
        int s0 = g_eidx[beg + e];
        uint2 v = gh2[(size_t)s0 * 32 + lane];
        float2 f0 = __half22float2(*reinterpret_cast<__half2*>(&v.x));
        float2 f1 = __half22float2(*reinterpret_cast<__half2*>(&v.y));
        acc.x += f0.x; acc.y += f0.y; acc.z += f1.x; acc.w += f1.y;
    }

    float sdi = g_dinv[w];
    const float4* b4 = reinterpret_cast<const float4*>(b);
    float4 bb = b4[lane];
    float4 o;
    o.x = fmaf(acc.x, sdi, bb.x);
    o.y = fmaf(acc.y, sdi, bb.y);
    o.z = fmaf(acc.z, sdi, bb.z);
    o.w = fmaf(acc.w, sdi, bb.w);
    reinterpret_cast<float4*>(out)[(size_t)w * 32 + lane] = o;
}

// ---------------- launch: cnt -> {gemm || scan -> fill} -> aggregate ----------

extern "C" void kernel_launch(void* const* d_in, const int* in_sizes, int n_in,
                              void* d_out, int out_size) {
    const float* x  = (const float*)d_in[0];
    const int*   ei = (const int*)d_in[1];     // int32 (JAX x64 disabled)
    const float* W  = (const float*)d_in[3];
    const float* b  = (const float*)d_in[4];
    float*       out = (float*)d_out;

    int n = in_sizes[0] / NIN;
    int E = in_sizes[1] / 2;
    int nb = (n + SCAN_B - 1) / SCAN_B;

    cudaStream_t s2;
    cudaEvent_t evC, evJ;
    cudaStreamCreateWithFlags(&s2, cudaStreamNonBlocking);
    cudaEventCreateWithFlags(&evC, cudaEventDisableTiming);
    cudaEventCreateWithFlags(&evJ, cudaEventDisableTiming);

    void* cnt_ptr = nullptr;
    cudaGetSymbolAddress(&cnt_ptr, g_cnt);
    cudaMemsetAsync(cnt_ptr, 0, (size_t)n * sizeof(int));
    cnt_count_kernel<<<(E + 255) / 256, 256>>>(ei, E, n);        // idx 0
    cudaEventRecord(evC, 0);

    // gemm needs only g_cnt -> forks right after cnt, overlaps scan+fill.
    cudaStreamWaitEvent(s2, evC, 0);
    gemm_mma_kernel<<<(n + 127) / 128, 256, 0, s2>>>(x, W, n);   // idx 1
    cudaEventRecord(evJ, s2);

    scan_fused_kernel<<<nb, SCAN_B>>>(n);                        // idx 2
    fill_kernel<<<(E + 255) / 256, 256>>>(ei, E, n);             // idx 3

    cudaStreamWaitEvent(0, evJ, 0);
    long long agg_threads = (long long)n * 32;
    aggregate_kernel<<<(int)((agg_threads + 255) / 256), 256>>>(out, b, n);  // idx 4
}